// round 1
// baseline (speedup 1.0000x reference)
#include <cuda_runtime.h>

// ResidualVectorQuantizer — exact fp32-order-replicating implementation.
// embeddings: [16, 128, 64, 64] f32   (d_in[0])
// codebooks : [8, 1024, 128]   f32   (d_in[1])
// out       : [16, 128, 64, 64] f32
//
// N = 65536 rows of E=128. For each of 8 codebooks: argmin_k of
//   d = (A - 2*dot(r,c_k)) + C_k   with fp32 rounding at each step,
// first-index tie-break, then res -= c[idx], quant += c[idx].

#define N_ROWS 65536
#define EDIM   128
#define KCB    1024
#define NCB    8
#define BM     128
#define BK     128
#define RT_PAD 132   // 132*4 = 528 bytes, 16B-aligned rows for float4 LDS

// Scratch (no allocation allowed) — 2 x 33.5 MB + norms
__device__ __align__(16) float g_res[N_ROWS * EDIM];
__device__ __align__(16) float g_quant[N_ROWS * EDIM];
__device__ float g_norms[NCB * KCB];

// ---------------------------------------------------------------------------
// Kernel 1: [B,E,H,W] -> row-major [N,E] residual init; zero quant.
// n = b*4096 + h*64 + w
// ---------------------------------------------------------------------------
__global__ void k_transpose_in(const float* __restrict__ emb) {
    __shared__ float s[32][33];
    int b   = blockIdx.z;
    int e0  = blockIdx.y * 32;
    int hw0 = blockIdx.x * 32;
    int tx = threadIdx.x, ty = threadIdx.y;   // (32, 8)
#pragma unroll
    for (int i = 0; i < 4; i++) {
        int e = e0 + ty + 8 * i;
        s[ty + 8 * i][tx] = emb[((size_t)(b * EDIM + e)) * 4096 + hw0 + tx];
    }
    __syncthreads();
#pragma unroll
    for (int i = 0; i < 4; i++) {
        int hw = hw0 + ty + 8 * i;
        size_t off = ((size_t)(b * 4096 + hw)) * EDIM + e0 + tx;
        g_res[off]   = s[tx][ty + 8 * i];
        g_quant[off] = 0.0f;
    }
}

// ---------------------------------------------------------------------------
// Kernel 2: code norms C_k = sum_e round(c*c), sequential e ascending.
// (Separate mul+add roundings — reference does cb*cb then sum, no FMA.)
// ---------------------------------------------------------------------------
__global__ void k_norms(const float* __restrict__ cb) {
    int idx = blockIdx.x * blockDim.x + threadIdx.x;
    if (idx >= NCB * KCB) return;
    const float* c = cb + (size_t)idx * EDIM;
    float acc = 0.0f;
    for (int e = 0; e < EDIM; e++) {
        float v = c[e];
        acc = __fadd_rn(acc, __fmul_rn(v, v));
    }
    g_norms[idx] = acc;
}

// ---------------------------------------------------------------------------
// Kernel 3: one codebook step. Block = 128 rows; full K=1024 in chunks of 128.
// 256 threads as 16(tx) x 16(ty); each thread: 8 rows x 8 codes register tile.
// Dot accumulation: strictly e-ascending FMA chain per (row, code).
// ---------------------------------------------------------------------------
__global__ void __launch_bounds__(256, 1)
k_step(const float* __restrict__ cb_all, int step) {
    extern __shared__ float sm[];
    float* Rt    = sm;                        // [E][RT_PAD]
    float* Ct    = sm + EDIM * RT_PAD;        // [E][RT_PAD]
    float* sA    = sm + 2 * EDIM * RT_PAD;    // [BM]
    float* redv  = sA + BM;                   // [BM*16]
    int*   redi  = (int*)(redv + BM * 16);    // [BM*16]
    int*   sBest = redi + BM * 16;            // [BM]

    const float* cb = cb_all + (size_t)step * KCB * EDIM;
    const float* nm = g_norms + step * KCB;
    int rowbase = blockIdx.x * BM;
    int t  = threadIdx.x;
    int tx = t & 15, ty = t >> 4;

    // Load residual tile, transposed to e-major.
    for (int v = t; v < BM * 32; v += 256) {
        int m = v >> 5, e4 = (v & 31) * 4;
        float4 r = *(const float4*)&g_res[((size_t)(rowbase + m)) * EDIM + e4];
        Rt[(e4 + 0) * RT_PAD + m] = r.x;
        Rt[(e4 + 1) * RT_PAD + m] = r.y;
        Rt[(e4 + 2) * RT_PAD + m] = r.z;
        Rt[(e4 + 3) * RT_PAD + m] = r.w;
    }
    __syncthreads();

    // A = ||r||^2 per row: sequential e ascending, round(mul) then add.
    if (t < BM) {
        float acc = 0.0f;
        for (int e = 0; e < EDIM; e++) {
            float v = Rt[e * RT_PAD + t];
            acc = __fadd_rn(acc, __fmul_rn(v, v));
        }
        sA[t] = acc;
    }
    __syncthreads();

    float areg[8];
#pragma unroll
    for (int i = 0; i < 8; i++) areg[i] = sA[ty * 8 + i];

    float best[8];
    int   bidx[8];
#pragma unroll
    for (int i = 0; i < 8; i++) { best[i] = 3.4e38f; bidx[i] = 0; }

    for (int kc = 0; kc < KCB; kc += BK) {
        __syncthreads();  // previous chunk's compute done before overwrite
        for (int v = t; v < BK * 32; v += 256) {
            int k = v >> 5, e4 = (v & 31) * 4;
            float4 c = *(const float4*)&cb[((size_t)(kc + k)) * EDIM + e4];
            Ct[(e4 + 0) * RT_PAD + k] = c.x;
            Ct[(e4 + 1) * RT_PAD + k] = c.y;
            Ct[(e4 + 2) * RT_PAD + k] = c.z;
            Ct[(e4 + 3) * RT_PAD + k] = c.w;
        }
        __syncthreads();

        float acc[8][8];
#pragma unroll
        for (int i = 0; i < 8; i++)
#pragma unroll
            for (int j = 0; j < 8; j++) acc[i][j] = 0.0f;

#pragma unroll 2
        for (int e = 0; e < EDIM; e++) {
            float4 r0 = *(float4*)&Rt[e * RT_PAD + ty * 8];
            float4 r1 = *(float4*)&Rt[e * RT_PAD + ty * 8 + 4];
            float4 c0 = *(float4*)&Ct[e * RT_PAD + tx * 8];
            float4 c1 = *(float4*)&Ct[e * RT_PAD + tx * 8 + 4];
            float rf[8] = {r0.x, r0.y, r0.z, r0.w, r1.x, r1.y, r1.z, r1.w};
            float cf[8] = {c0.x, c0.y, c0.z, c0.w, c1.x, c1.y, c1.z, c1.w};
#pragma unroll
            for (int i = 0; i < 8; i++)
#pragma unroll
                for (int j = 0; j < 8; j++)
                    acc[i][j] = __fmaf_rn(rf[i], cf[j], acc[i][j]);
        }

        // d = (A - 2*dot) + C, fp32 roundings matching the reference graph.
        float cn[8];
#pragma unroll
        for (int j = 0; j < 8; j++) cn[j] = nm[kc + tx * 8 + j];
#pragma unroll
        for (int i = 0; i < 8; i++) {
#pragma unroll
            for (int j = 0; j < 8; j++) {
                float d = __fadd_rn(__fsub_rn(areg[i], 2.0f * acc[i][j]), cn[j]);
                int kidx = kc + tx * 8 + j;
                if (d < best[i]) { best[i] = d; bidx[i] = kidx; }  // ascending scan => first-min
            }
        }
    }
    __syncthreads();

    // Cross-thread argmin reduction (first-index tie-break).
#pragma unroll
    for (int i = 0; i < 8; i++) {
        redv[(ty * 8 + i) * 16 + tx] = best[i];
        redi[(ty * 8 + i) * 16 + tx] = bidx[i];
    }
    __syncthreads();
    if (t < BM) {
        float bv = redv[t * 16];
        int   bi = redi[t * 16];
#pragma unroll
        for (int x = 1; x < 16; x++) {
            float v  = redv[t * 16 + x];
            int   ix = redi[t * 16 + x];
            if (v < bv || (v == bv && ix < bi)) { bv = v; bi = ix; }
        }
        sBest[t] = bi;
    }
    __syncthreads();

    // res -= dec; quant += dec  (exact elementwise ops, matching reference)
    for (int v = t; v < BM * 32; v += 256) {
        int m = v >> 5, e4 = (v & 31) * 4;
        const float4 dec = *(const float4*)&cb[((size_t)sBest[m]) * EDIM + e4];
        size_t off = ((size_t)(rowbase + m)) * EDIM + e4;
        float4 r = *(float4*)&g_res[off];
        float4 q = *(float4*)&g_quant[off];
        r.x = __fsub_rn(r.x, dec.x); r.y = __fsub_rn(r.y, dec.y);
        r.z = __fsub_rn(r.z, dec.z); r.w = __fsub_rn(r.w, dec.w);
        q.x = __fadd_rn(q.x, dec.x); q.y = __fadd_rn(q.y, dec.y);
        q.z = __fadd_rn(q.z, dec.z); q.w = __fadd_rn(q.w, dec.w);
        *(float4*)&g_res[off]   = r;
        *(float4*)&g_quant[off] = q;
    }
}

// ---------------------------------------------------------------------------
// Kernel 4: quant [N,E] -> out [B,E,H,W]
// ---------------------------------------------------------------------------
__global__ void k_transpose_out(float* __restrict__ out) {
    __shared__ float s[32][33];
    int b   = blockIdx.z;
    int e0  = blockIdx.y * 32;
    int hw0 = blockIdx.x * 32;
    int tx = threadIdx.x, ty = threadIdx.y;
#pragma unroll
    for (int i = 0; i < 4; i++) {
        int hw = hw0 + ty + 8 * i;
        s[ty + 8 * i][tx] = g_quant[((size_t)(b * 4096 + hw)) * EDIM + e0 + tx];
    }
    __syncthreads();
#pragma unroll
    for (int i = 0; i < 4; i++) {
        int e = e0 + ty + 8 * i;
        out[((size_t)(b * EDIM + e)) * 4096 + hw0 + tx] = s[tx][ty + 8 * i];
    }
}

// ---------------------------------------------------------------------------
extern "C" void kernel_launch(void* const* d_in, const int* in_sizes, int n_in,
                              void* d_out, int out_size) {
    (void)in_sizes; (void)n_in; (void)out_size;
    const float* emb = (const float*)d_in[0];
    const float* cb  = (const float*)d_in[1];
    float* out = (float*)d_out;

    const int smem_bytes = (2 * EDIM * RT_PAD + BM + BM * 16) * 4  // Rt,Ct,sA,redv
                         + BM * 16 * 4 + BM * 4;                   // redi, sBest
    cudaFuncSetAttribute(k_step, cudaFuncAttributeMaxDynamicSharedMemorySize,
                         smem_bytes);

    dim3 tb(32, 8);
    k_transpose_in<<<dim3(128, 4, 16), tb>>>(emb);
    k_norms<<<(NCB * KCB + 255) / 256, 256>>>(cb);
    for (int i = 0; i < NCB; i++)
        k_step<<<N_ROWS / BM, 256, smem_bytes>>>(cb, i);
    k_transpose_out<<<dim3(128, 4, 16), tb>>>(out);
}

// round 2
// speedup vs baseline: 1.1824x; 1.1824x over previous
#include <cuda_runtime.h>

// ResidualVectorQuantizer — fp32-order-exact, FFMA2 (fma.rn.f32x2) mainloop.
// embeddings: [16, 128, 64, 64] f32   (d_in[0])
// codebooks : [8, 1024, 128]   f32   (d_in[1])
// out       : [16, 128, 64, 64] f32

#define N_ROWS 65536
#define EDIM   128
#define KCB    1024
#define NCB    8
#define BM     256   // rows per block
#define BK     128   // codes per chunk
#define RTP    260   // Rt row pitch (256 + 4), 16B-aligned
#define CTP    132   // Ct row pitch (128 + 4), 16B-aligned

__device__ __align__(16) float g_res[N_ROWS * EDIM];
__device__ __align__(16) float g_quant[N_ROWS * EDIM];
__device__ float g_norms[NCB * KCB];

// packed fp32x2 FMA: d = a*b + d, per-lane IEEE rn (bit-exact per element)
#define FMA2(d, a, b) \
    asm("fma.rn.f32x2 %0, %1, %2, %0;" : "+l"(d) : "l"(a), "l"(b))
#define DUP2(d, s) \
    asm("mov.b64 %0, {%1, %1};" : "=l"(d) : "f"(s))
#define UNPK2(lo, hi, v) \
    asm("mov.b64 {%0, %1}, %2;" : "=f"(lo), "=f"(hi) : "l"(v))

// ---------------------------------------------------------------------------
// Kernel 1: [B,E,H,W] -> row-major [N,E] residual init; zero quant.
// ---------------------------------------------------------------------------
__global__ void k_transpose_in(const float* __restrict__ emb) {
    __shared__ float s[32][33];
    int b = blockIdx.z, e0 = blockIdx.y * 32, hw0 = blockIdx.x * 32;
    int tx = threadIdx.x, ty = threadIdx.y;   // (32, 8)
#pragma unroll
    for (int i = 0; i < 4; i++) {
        int e = e0 + ty + 8 * i;
        s[ty + 8 * i][tx] = emb[((size_t)(b * EDIM + e)) * 4096 + hw0 + tx];
    }
    __syncthreads();
#pragma unroll
    for (int i = 0; i < 4; i++) {
        int hw = hw0 + ty + 8 * i;
        size_t off = ((size_t)(b * 4096 + hw)) * EDIM + e0 + tx;
        g_res[off]   = s[tx][ty + 8 * i];
        g_quant[off] = 0.0f;
    }
}

// ---------------------------------------------------------------------------
// Kernel 2: code norms C_k = sum_e round(c*c), e ascending (mul then add).
// ---------------------------------------------------------------------------
__global__ void k_norms(const float* __restrict__ cb) {
    int idx = blockIdx.x * blockDim.x + threadIdx.x;
    if (idx >= NCB * KCB) return;
    const float* c = cb + (size_t)idx * EDIM;
    float acc = 0.0f;
    for (int e = 0; e < EDIM; e++) {
        float v = c[e];
        acc = __fadd_rn(acc, __fmul_rn(v, v));
    }
    g_norms[idx] = acc;
}

// ---------------------------------------------------------------------------
// Kernel 3: one codebook step. Block = 256 rows, 256 threads (16 tx x 16 ty).
// Thread tile: 16 rows (8 f32x2 pairs) x 8 codes. Chains strictly e-ascending.
// ---------------------------------------------------------------------------
__global__ void __launch_bounds__(256, 1)
k_step(const float* __restrict__ cb_all, int step) {
    extern __shared__ float sm[];
    float* Rt    = sm;                       // [E][RTP]
    float* Ct    = sm + EDIM * RTP;          // [E][CTP]  (reused for reduction)
    float* sA    = sm + EDIM * RTP + EDIM * CTP;   // [BM]
    int*   sBest = (int*)(sA + BM);          // [BM]
    float* redv  = Ct;                        // alias: [BM][16]
    int*   redi  = (int*)(Ct + BM * 16);      // alias: [BM][16]

    const float* cb = cb_all + (size_t)step * KCB * EDIM;
    const float* nm = g_norms + step * KCB;
    int rowbase = blockIdx.x * BM;
    int t  = threadIdx.x;
    int tx = t & 15, ty = t >> 4;

    // Load residual tile, transposed to e-major.
    for (int v = t; v < BM * 32; v += 256) {
        int m = v >> 5, e4 = (v & 31) * 4;
        float4 r = *(const float4*)&g_res[((size_t)(rowbase + m)) * EDIM + e4];
        Rt[(e4 + 0) * RTP + m] = r.x;
        Rt[(e4 + 1) * RTP + m] = r.y;
        Rt[(e4 + 2) * RTP + m] = r.z;
        Rt[(e4 + 3) * RTP + m] = r.w;
    }
    __syncthreads();

    // A = ||r||^2 per row: e ascending, round(mul) then add.
    {
        float acc = 0.0f;
        for (int e = 0; e < EDIM; e++) {
            float v = Rt[e * RTP + t];
            acc = __fadd_rn(acc, __fmul_rn(v, v));
        }
        sA[t] = acc;
    }

    float best[16];
    int   bidx[16];
#pragma unroll
    for (int i = 0; i < 16; i++) { best[i] = 3.4e38f; bidx[i] = 0; }

    for (int kc = 0; kc < KCB; kc += BK) {
        __syncthreads();  // prior chunk compute done before Ct overwrite
        for (int v = t; v < BK * 32; v += 256) {
            int k = v >> 5, e4 = (v & 31) * 4;
            float4 c = *(const float4*)&cb[((size_t)(kc + k)) * EDIM + e4];
            Ct[(e4 + 0) * CTP + k] = c.x;
            Ct[(e4 + 1) * CTP + k] = c.y;
            Ct[(e4 + 2) * CTP + k] = c.z;
            Ct[(e4 + 3) * CTP + k] = c.w;
        }
        __syncthreads();

        unsigned long long acc[64];   // [row_pair 8][code 8]
#pragma unroll
        for (int i = 0; i < 64; i++) acc[i] = 0ull;

#pragma unroll 1
        for (int e = 0; e < EDIM; e++) {
            const float* rb = &Rt[e * RTP + ty * 16];
            ulonglong2 ra = *(const ulonglong2*)(rb);
            ulonglong2 rc = *(const ulonglong2*)(rb + 4);
            ulonglong2 re = *(const ulonglong2*)(rb + 8);
            ulonglong2 rg = *(const ulonglong2*)(rb + 12);
            unsigned long long rf[8] = {ra.x, ra.y, rc.x, rc.y,
                                        re.x, re.y, rg.x, rg.y};
            const float* cbse = &Ct[e * CTP + tx * 8];
            float4 c0 = *(const float4*)(cbse);
            float4 c1 = *(const float4*)(cbse + 4);
            float cf[8] = {c0.x, c0.y, c0.z, c0.w, c1.x, c1.y, c1.z, c1.w};
            unsigned long long cd[8];
#pragma unroll
            for (int j = 0; j < 8; j++) DUP2(cd[j], cf[j]);
#pragma unroll
            for (int ip = 0; ip < 8; ip++)
#pragma unroll
                for (int j = 0; j < 8; j++)
                    FMA2(acc[ip * 8 + j], rf[ip], cd[j]);
        }

        // d = (A - 2*dot) + C, same rounding graph as reference.
        float cn[8];
#pragma unroll
        for (int j = 0; j < 8; j++) cn[j] = nm[kc + tx * 8 + j];
#pragma unroll
        for (int ip = 0; ip < 8; ip++) {
            float A0 = sA[ty * 16 + ip * 2];
            float A1 = sA[ty * 16 + ip * 2 + 1];
#pragma unroll
            for (int j = 0; j < 8; j++) {
                float lo, hi;
                UNPK2(lo, hi, acc[ip * 8 + j]);
                int kidx = kc + tx * 8 + j;
                float d0 = __fadd_rn(__fsub_rn(A0, 2.0f * lo), cn[j]);
                float d1 = __fadd_rn(__fsub_rn(A1, 2.0f * hi), cn[j]);
                if (d0 < best[ip * 2])     { best[ip * 2]     = d0; bidx[ip * 2]     = kidx; }
                if (d1 < best[ip * 2 + 1]) { best[ip * 2 + 1] = d1; bidx[ip * 2 + 1] = kidx; }
            }
        }
    }
    __syncthreads();   // mainloop done; Ct region now reusable for reduction

    // Cross-thread argmin reduction (first-index tie-break).
#pragma unroll
    for (int i = 0; i < 16; i++) {
        redv[(ty * 16 + i) * 16 + tx] = best[i];
        redi[(ty * 16 + i) * 16 + tx] = bidx[i];
    }
    __syncthreads();
    {
        float bv = redv[t * 16];
        int   bi = redi[t * 16];
#pragma unroll
        for (int x = 1; x < 16; x++) {
            float v  = redv[t * 16 + x];
            int   ix = redi[t * 16 + x];
            if (v < bv || (v == bv && ix < bi)) { bv = v; bi = ix; }
        }
        sBest[t] = bi;
    }
    __syncthreads();

    // res -= dec; quant += dec
    for (int v = t; v < BM * 32; v += 256) {
        int m = v >> 5, e4 = (v & 31) * 4;
        const float4 dec = *(const float4*)&cb[((size_t)sBest[m]) * EDIM + e4];
        size_t off = ((size_t)(rowbase + m)) * EDIM + e4;
        float4 r = *(float4*)&g_res[off];
        float4 q = *(float4*)&g_quant[off];
        r.x = __fsub_rn(r.x, dec.x); r.y = __fsub_rn(r.y, dec.y);
        r.z = __fsub_rn(r.z, dec.z); r.w = __fsub_rn(r.w, dec.w);
        q.x = __fadd_rn(q.x, dec.x); q.y = __fadd_rn(q.y, dec.y);
        q.z = __fadd_rn(q.z, dec.z); q.w = __fadd_rn(q.w, dec.w);
        *(float4*)&g_res[off]   = r;
        *(float4*)&g_quant[off] = q;
    }
}

// ---------------------------------------------------------------------------
// Kernel 4: quant [N,E] -> out [B,E,H,W]
// ---------------------------------------------------------------------------
__global__ void k_transpose_out(float* __restrict__ out) {
    __shared__ float s[32][33];
    int b = blockIdx.z, e0 = blockIdx.y * 32, hw0 = blockIdx.x * 32;
    int tx = threadIdx.x, ty = threadIdx.y;
#pragma unroll
    for (int i = 0; i < 4; i++) {
        int hw = hw0 + ty + 8 * i;
        s[ty + 8 * i][tx] = g_quant[((size_t)(b * 4096 + hw)) * EDIM + e0 + tx];
    }
    __syncthreads();
#pragma unroll
    for (int i = 0; i < 4; i++) {
        int e = e0 + ty + 8 * i;
        out[((size_t)(b * EDIM + e)) * 4096 + hw0 + tx] = s[tx][ty + 8 * i];
    }
}

// ---------------------------------------------------------------------------
extern "C" void kernel_launch(void* const* d_in, const int* in_sizes, int n_in,
                              void* d_out, int out_size) {
    (void)in_sizes; (void)n_in; (void)out_size;
    const float* emb = (const float*)d_in[0];
    const float* cb  = (const float*)d_in[1];
    float* out = (float*)d_out;

    const int smem_bytes = (EDIM * RTP + EDIM * CTP + BM) * 4 + BM * 4;
    cudaFuncSetAttribute(k_step, cudaFuncAttributeMaxDynamicSharedMemorySize,
                         smem_bytes);

    dim3 tb(32, 8);
    k_transpose_in<<<dim3(128, 4, 16), tb>>>(emb);
    k_norms<<<(NCB * KCB + 255) / 256, 256>>>(cb);
    for (int i = 0; i < NCB; i++)
        k_step<<<N_ROWS / BM, 256, smem_bytes>>>(cb, i);
    k_transpose_out<<<dim3(128, 4, 16), tb>>>(out);
}

// round 3
// speedup vs baseline: 1.1835x; 1.0009x over previous
#include <cuda_runtime.h>

// ResidualVectorQuantizer — fp32-order-exact, FFMA2 (fma.rn.f32x2) mainloop.
// embeddings: [16, 128, 64, 64] f32   (d_in[0])
// codebooks : [8, 1024, 128]   f32   (d_in[1])
// out       : [16, 128, 64, 64] f32

#define N_ROWS 65536
#define EDIM   128
#define KCB    1024
#define NCB    8
#define BM     256   // rows per block
#define BK     128   // codes per chunk
#define RTP    260   // Rt row pitch (256 + 4), 16B-aligned
#define CTP    132   // Ct row pitch (128 + 4), 16B-aligned

__device__ __align__(16) float g_res[N_ROWS * EDIM];
__device__ __align__(16) float g_quant[N_ROWS * EDIM];
__device__ float g_norms[NCB * KCB];

// packed fp32x2 FMA: d = a*b + d, per-lane IEEE rn (bit-exact per element)
#define FMA2(d, a, b) \
    asm("fma.rn.f32x2 %0, %1, %2, %0;" : "+l"(d) : "l"(a), "l"(b))
#define DUP2(d, s) \
    asm("mov.b64 %0, {%1, %1};" : "=l"(d) : "f"(s))
#define UNPK2(lo, hi, v) \
    asm("mov.b64 {%0, %1}, %2;" : "=f"(lo), "=f"(hi) : "l"(v))

// ---------------------------------------------------------------------------
// Kernel 1: [B,E,H,W] -> row-major [N,E] residual init; zero quant.
// ---------------------------------------------------------------------------
__global__ void k_transpose_in(const float* __restrict__ emb) {
    __shared__ float s[32][33];
    int b = blockIdx.z, e0 = blockIdx.y * 32, hw0 = blockIdx.x * 32;
    int tx = threadIdx.x, ty = threadIdx.y;   // (32, 8)
#pragma unroll
    for (int i = 0; i < 4; i++) {
        int e = e0 + ty + 8 * i;
        s[ty + 8 * i][tx] = emb[((size_t)(b * EDIM + e)) * 4096 + hw0 + tx];
    }
    __syncthreads();
#pragma unroll
    for (int i = 0; i < 4; i++) {
        int hw = hw0 + ty + 8 * i;
        size_t off = ((size_t)(b * 4096 + hw)) * EDIM + e0 + tx;
        g_res[off]   = s[tx][ty + 8 * i];
        g_quant[off] = 0.0f;
    }
}

// ---------------------------------------------------------------------------
// Kernel 2: code norms C_k = sum_e round(c*c), e ascending (mul then add).
// ---------------------------------------------------------------------------
__global__ void k_norms(const float* __restrict__ cb) {
    int idx = blockIdx.x * blockDim.x + threadIdx.x;
    if (idx >= NCB * KCB) return;
    const float* c = cb + (size_t)idx * EDIM;
    float acc = 0.0f;
    for (int e = 0; e < EDIM; e++) {
        float v = c[e];
        acc = __fadd_rn(acc, __fmul_rn(v, v));
    }
    g_norms[idx] = acc;
}

// ---------------------------------------------------------------------------
// Kernel 3: one codebook step. Block = 256 rows, 256 threads (16 tx x 16 ty).
// Thread tile: 16 rows (8 f32x2 pairs) x 8 codes. Chains strictly e-ascending.
// ---------------------------------------------------------------------------
__global__ void __launch_bounds__(256, 1)
k_step(const float* __restrict__ cb_all, int step) {
    extern __shared__ float sm[];
    float* Rt    = sm;                       // [E][RTP]
    float* Ct    = sm + EDIM * RTP;          // [E][CTP]  (reused for reduction)
    float* sA    = sm + EDIM * RTP + EDIM * CTP;   // [BM]
    int*   sBest = (int*)(sA + BM);          // [BM]
    float* redv  = Ct;                        // alias: [BM][16]
    int*   redi  = (int*)(Ct + BM * 16);      // alias: [BM][16]

    const float* cb = cb_all + (size_t)step * KCB * EDIM;
    const float* nm = g_norms + step * KCB;
    int rowbase = blockIdx.x * BM;
    int t  = threadIdx.x;
    int tx = t & 15, ty = t >> 4;

    // Load residual tile, transposed to e-major.
    for (int v = t; v < BM * 32; v += 256) {
        int m = v >> 5, e4 = (v & 31) * 4;
        float4 r = *(const float4*)&g_res[((size_t)(rowbase + m)) * EDIM + e4];
        Rt[(e4 + 0) * RTP + m] = r.x;
        Rt[(e4 + 1) * RTP + m] = r.y;
        Rt[(e4 + 2) * RTP + m] = r.z;
        Rt[(e4 + 3) * RTP + m] = r.w;
    }
    __syncthreads();

    // A = ||r||^2 per row: e ascending, round(mul) then add.
    {
        float acc = 0.0f;
        for (int e = 0; e < EDIM; e++) {
            float v = Rt[e * RTP + t];
            acc = __fadd_rn(acc, __fmul_rn(v, v));
        }
        sA[t] = acc;
    }

    float best[16];
    int   bidx[16];
#pragma unroll
    for (int i = 0; i < 16; i++) { best[i] = 3.4e38f; bidx[i] = 0; }

    for (int kc = 0; kc < KCB; kc += BK) {
        __syncthreads();  // prior chunk compute done before Ct overwrite
        for (int v = t; v < BK * 32; v += 256) {
            int k = v >> 5, e4 = (v & 31) * 4;
            float4 c = *(const float4*)&cb[((size_t)(kc + k)) * EDIM + e4];
            Ct[(e4 + 0) * CTP + k] = c.x;
            Ct[(e4 + 1) * CTP + k] = c.y;
            Ct[(e4 + 2) * CTP + k] = c.z;
            Ct[(e4 + 3) * CTP + k] = c.w;
        }
        __syncthreads();

        unsigned long long acc[64];   // [row_pair 8][code 8]
#pragma unroll
        for (int i = 0; i < 64; i++) acc[i] = 0ull;

#pragma unroll 1
        for (int e = 0; e < EDIM; e++) {
            const float* rb = &Rt[e * RTP + ty * 16];
            ulonglong2 ra = *(const ulonglong2*)(rb);
            ulonglong2 rc = *(const ulonglong2*)(rb + 4);
            ulonglong2 re = *(const ulonglong2*)(rb + 8);
            ulonglong2 rg = *(const ulonglong2*)(rb + 12);
            unsigned long long rf[8] = {ra.x, ra.y, rc.x, rc.y,
                                        re.x, re.y, rg.x, rg.y};
            const float* cbse = &Ct[e * CTP + tx * 8];
            float4 c0 = *(const float4*)(cbse);
            float4 c1 = *(const float4*)(cbse + 4);
            float cf[8] = {c0.x, c0.y, c0.z, c0.w, c1.x, c1.y, c1.z, c1.w};
            unsigned long long cd[8];
#pragma unroll
            for (int j = 0; j < 8; j++) DUP2(cd[j], cf[j]);
#pragma unroll
            for (int ip = 0; ip < 8; ip++)
#pragma unroll
                for (int j = 0; j < 8; j++)
                    FMA2(acc[ip * 8 + j], rf[ip], cd[j]);
        }

        // d = (A - 2*dot) + C, same rounding graph as reference.
        float cn[8];
#pragma unroll
        for (int j = 0; j < 8; j++) cn[j] = nm[kc + tx * 8 + j];
#pragma unroll
        for (int ip = 0; ip < 8; ip++) {
            float A0 = sA[ty * 16 + ip * 2];
            float A1 = sA[ty * 16 + ip * 2 + 1];
#pragma unroll
            for (int j = 0; j < 8; j++) {
                float lo, hi;
                UNPK2(lo, hi, acc[ip * 8 + j]);
                int kidx = kc + tx * 8 + j;
                float d0 = __fadd_rn(__fsub_rn(A0, 2.0f * lo), cn[j]);
                float d1 = __fadd_rn(__fsub_rn(A1, 2.0f * hi), cn[j]);
                if (d0 < best[ip * 2])     { best[ip * 2]     = d0; bidx[ip * 2]     = kidx; }
                if (d1 < best[ip * 2 + 1]) { best[ip * 2 + 1] = d1; bidx[ip * 2 + 1] = kidx; }
            }
        }
    }
    __syncthreads();   // mainloop done; Ct region now reusable for reduction

    // Cross-thread argmin reduction (first-index tie-break).
#pragma unroll
    for (int i = 0; i < 16; i++) {
        redv[(ty * 16 + i) * 16 + tx] = best[i];
        redi[(ty * 16 + i) * 16 + tx] = bidx[i];
    }
    __syncthreads();
    {
        float bv = redv[t * 16];
        int   bi = redi[t * 16];
#pragma unroll
        for (int x = 1; x < 16; x++) {
            float v  = redv[t * 16 + x];
            int   ix = redi[t * 16 + x];
            if (v < bv || (v == bv && ix < bi)) { bv = v; bi = ix; }
        }
        sBest[t] = bi;
    }
    __syncthreads();

    // res -= dec; quant += dec
    for (int v = t; v < BM * 32; v += 256) {
        int m = v >> 5, e4 = (v & 31) * 4;
        const float4 dec = *(const float4*)&cb[((size_t)sBest[m]) * EDIM + e4];
        size_t off = ((size_t)(rowbase + m)) * EDIM + e4;
        float4 r = *(float4*)&g_res[off];
        float4 q = *(float4*)&g_quant[off];
        r.x = __fsub_rn(r.x, dec.x); r.y = __fsub_rn(r.y, dec.y);
        r.z = __fsub_rn(r.z, dec.z); r.w = __fsub_rn(r.w, dec.w);
        q.x = __fadd_rn(q.x, dec.x); q.y = __fadd_rn(q.y, dec.y);
        q.z = __fadd_rn(q.z, dec.z); q.w = __fadd_rn(q.w, dec.w);
        *(float4*)&g_res[off]   = r;
        *(float4*)&g_quant[off] = q;
    }
}

// ---------------------------------------------------------------------------
// Kernel 4: quant [N,E] -> out [B,E,H,W]
// ---------------------------------------------------------------------------
__global__ void k_transpose_out(float* __restrict__ out) {
    __shared__ float s[32][33];
    int b = blockIdx.z, e0 = blockIdx.y * 32, hw0 = blockIdx.x * 32;
    int tx = threadIdx.x, ty = threadIdx.y;
#pragma unroll
    for (int i = 0; i < 4; i++) {
        int hw = hw0 + ty + 8 * i;
        s[ty + 8 * i][tx] = g_quant[((size_t)(b * 4096 + hw)) * EDIM + e0 + tx];
    }
    __syncthreads();
#pragma unroll
    for (int i = 0; i < 4; i++) {
        int e = e0 + ty + 8 * i;
        out[((size_t)(b * EDIM + e)) * 4096 + hw0 + tx] = s[tx][ty + 8 * i];
    }
}

// ---------------------------------------------------------------------------
extern "C" void kernel_launch(void* const* d_in, const int* in_sizes, int n_in,
                              void* d_out, int out_size) {
    (void)in_sizes; (void)n_in; (void)out_size;
    const float* emb = (const float*)d_in[0];
    const float* cb  = (const float*)d_in[1];
    float* out = (float*)d_out;

    const int smem_bytes = (EDIM * RTP + EDIM * CTP + BM) * 4 + BM * 4;
    cudaFuncSetAttribute(k_step, cudaFuncAttributeMaxDynamicSharedMemorySize,
                         smem_bytes);

    dim3 tb(32, 8);
    k_transpose_in<<<dim3(128, 4, 16), tb>>>(emb);
    k_norms<<<(NCB * KCB + 255) / 256, 256>>>(cb);
    for (int i = 0; i < NCB; i++)
        k_step<<<N_ROWS / BM, 256, smem_bytes>>>(cb, i);
    k_transpose_out<<<dim3(128, 4, 16), tb>>>(out);
}